// round 2
// baseline (speedup 1.0000x reference)
#include <cuda_runtime.h>

// Problem constants
#define TT     64
#define CC     32
#define HDIM   24
#define BB     16384
#define FF     2048
#define HHEAD  48

// Gram kernel tiling
#define CHUNKS        16
#define ROWS_PER_CTA  (BB / CHUNKS)      // 1024
#define TILE_R        64
#define TSTRIDE       68                 // padded transposed-smem row stride (floats)
#define NTILES        (ROWS_PER_CTA / TILE_R)

// Scratch (device globals: no allocation allowed)
__device__ float g_G[TT * CC * CC];
__device__ float g_s[TT * CC];
__device__ float g_tails[TT];

// Packed fp32x2 FMA (Blackwell): d = a*b + d elementwise on two packed f32
__device__ __forceinline__ void ffma2(unsigned long long &d,
                                      unsigned long long a,
                                      unsigned long long b) {
    asm("fma.rn.f32x2 %0, %1, %2, %0;" : "+l"(d) : "l"(a), "l"(b));
}

__device__ __forceinline__ float2 unpack2(unsigned long long v) {
    float2 r;
    asm("mov.b64 {%0, %1}, %2;" : "=f"(r.x), "=f"(r.y) : "l"(v));
    return r;
}

__global__ void zero_kernel() {
    int i = blockIdx.x * blockDim.x + threadIdx.x;
    if (i < TT * CC * CC) g_G[i] = 0.f;
    if (i < TT * CC)      g_s[i] = 0.f;
    if (i < TT)           g_tails[i] = 0.f;
}

// Kernel 1: per-t Gram matrix G_t = X^T X and column sums s_t over a B-chunk.
// Grid: (TT, CHUNKS), 256 threads.
// Smem tile is stored TRANSPOSED: xs[col][row], row stride 68 floats so that
//   - STS.128 fills are conflict-free-throughput (8 distinct 4-bank groups)
//   - per-column LDS.128 reads (cols spaced 8 apart) hit distinct bank groups
// Compute: 4 groups of 64 threads; thread tile = 4x4 of G, columns {q, q+8, q+16, q+24}.
// f32x2 lanes are paired along rows -> no operand duplication MOVs.
__global__ void __launch_bounds__(256, 2)
gram_kernel(const float* __restrict__ x, const int* __restrict__ clusters) {
    __shared__ float xs[2][CC * TSTRIDE];
    __shared__ int cidx[CC];

    const int t   = blockIdx.x;
    const int tid = threadIdx.x;
    if (tid < CC) cidx[tid] = clusters[t * CC + tid];
    __syncthreads();

    // ---- loader mapping: thread -> (col, 8 rows) ----
    const int lcol   = tid & 31;
    const int lrow0  = (tid >> 5) * 8;            // 8 rows per thread per tile
    const long rbase = (long)blockIdx.y * ROWS_PER_CTA;
    const float* __restrict__ xcol = x + cidx[lcol];

    // ---- compute mapping ----
    const int grp = tid >> 6;                      // 0..3 (row-chunk subset)
    const int g   = tid & 63;
    const int i0  = g >> 3;                        // 0..7
    const int j0  = g & 7;                         // 0..7

    unsigned long long acc[4][4][2];
#pragma unroll
    for (int a = 0; a < 4; a++)
#pragma unroll
        for (int b = 0; b < 4; b++) { acc[a][b][0] = 0ull; acc[a][b][1] = 0ull; }

    float ld[8];
    float ssum = 0.f;

    // prefetch tile 0
#pragma unroll
    for (int rr = 0; rr < 8; rr++)
        ld[rr] = xcol[(rbase + lrow0 + rr) * FF];

    for (int tile = 0; tile < NTILES; tile++) {
        const int buf = tile & 1;
        // store prefetched rows (transposed) as two STS.128
        float4* dst = (float4*)&xs[buf][lcol * TSTRIDE + lrow0];
        dst[0] = make_float4(ld[0], ld[1], ld[2], ld[3]);
        dst[1] = make_float4(ld[4], ld[5], ld[6], ld[7]);
#pragma unroll
        for (int rr = 0; rr < 8; rr++) ssum += ld[rr];

        // prefetch next tile (hides DRAM latency behind this tile's compute)
        if (tile + 1 < NTILES) {
            const long rb = rbase + (long)(tile + 1) * TILE_R + lrow0;
#pragma unroll
            for (int rr = 0; rr < 8; rr++) ld[rr] = xcol[(rb + rr) * FF];
        }
        __syncthreads();

        const float* __restrict__ xb = xs[buf];
#pragma unroll
        for (int m = 0; m < 4; m++) {
            const int r = grp * 4 + m * 16;        // 4-row chunk for this group
            ulonglong2 av[4], bv[4];
#pragma unroll
            for (int k = 0; k < 4; k++) {
                av[k] = *(const ulonglong2*)&xb[(i0 + 8 * k) * TSTRIDE + r];
                bv[k] = *(const ulonglong2*)&xb[(j0 + 8 * k) * TSTRIDE + r];
            }
#pragma unroll
            for (int ik = 0; ik < 4; ik++)
#pragma unroll
                for (int jk = 0; jk < 4; jk++) {
                    ffma2(acc[ik][jk][0], av[ik].x, bv[jk].x);
                    ffma2(acc[ik][jk][1], av[ik].y, bv[jk].y);
                }
        }
        __syncthreads();
    }

    // reduce pairs and accumulate into global Gram
    float* __restrict__ Gt = g_G + t * CC * CC;
#pragma unroll
    for (int ik = 0; ik < 4; ik++)
#pragma unroll
        for (int jk = 0; jk < 4; jk++) {
            float2 p0 = unpack2(acc[ik][jk][0]);
            float2 p1 = unpack2(acc[ik][jk][1]);
            float v = (p0.x + p0.y) + (p1.x + p1.y);
            atomicAdd(&Gt[(i0 + 8 * ik) * CC + (j0 + 8 * jk)], v);
        }
    atomicAdd(&g_s[t * CC + lcol], ssum);
}

// Kernel 2: per-t finalize. A = M M^T - I, k = M hb + vb,
// SSR = sum_c (A^T G A)_cc + 2 (s A).k + B |k|^2 ; tails = 0.5*log(SSR/(B*C)).
// Grid: TT blocks x 32 threads (thread c owns column c of A).
__global__ void finalize_kernel(const float* __restrict__ Wt,
                                const float* __restrict__ hb,
                                const float* __restrict__ vb,
                                float* __restrict__ out) {
    const int t = blockIdx.x;
    const int c = threadIdx.x;  // 0..31

    __shared__ float Ms[CC * HDIM];   // Wt[t]
    __shared__ float Gs[CC * CC];
    __shared__ float ss[CC];

    for (int i = c; i < CC * HDIM; i += 32) Ms[i] = Wt[t * CC * HDIM + i];
    for (int i = c; i < CC * CC; i += 32)   Gs[i] = g_G[t * CC * CC + i];
    ss[c] = g_s[t * CC + c];
    __syncwarp();

    // hoist this thread's M row (avoids 8-way-conflicted lane-varying LDS in loops)
    float Mc[HDIM];
#pragma unroll
    for (int h = 0; h < HDIM; h++) Mc[h] = Ms[c * HDIM + h];

    float a[CC];
#pragma unroll
    for (int i = 0; i < CC; i++) {
        float accv = 0.f;
#pragma unroll
        for (int h = 0; h < HDIM; h++) accv += Ms[i * HDIM + h] * Mc[h];
        a[i] = (i == c) ? (accv - 1.f) : accv;
    }

    float quad = 0.f, sA = 0.f;
#pragma unroll
    for (int i = 0; i < CC; i++) {
        float d = 0.f;
#pragma unroll
        for (int j = 0; j < CC; j++) d += Gs[i * CC + j] * a[j];
        quad += a[i] * d;
        sA   += ss[i] * a[i];
    }

    float kc = vb[t * CC + c];
#pragma unroll
    for (int h = 0; h < HDIM; h++) kc += hb[t * HDIM + h] * Mc[h];

    float contrib = quad + 2.f * kc * sA + (float)BB * kc * kc;
#pragma unroll
    for (int off = 16; off; off >>= 1)
        contrib += __shfl_xor_sync(0xffffffffu, contrib, off);

    if (c == 0) {
        float msr  = contrib * (1.f / (float)(BB * CC));
        float tail = 0.5f * logf(msr);   // log(sqrt(msr))
        g_tails[t] = tail;
        out[TT + t] = tail;              // tails occupy out[64..127]
    }
}

// Kernel 3: head. hh = tails @ Wh + hbh ; head_out = hh @ Wh^T + vbh.
__global__ void head_kernel(const float* __restrict__ Wh,
                            const float* __restrict__ hbh,
                            const float* __restrict__ vbh,
                            float* __restrict__ out) {
    __shared__ float hh[HHEAD];
    __shared__ float tl[TT];
    const int tid = threadIdx.x;  // 64 threads
    tl[tid] = g_tails[tid];
    __syncthreads();
    if (tid < HHEAD) {
        float accv = hbh[tid];
#pragma unroll 8
        for (int t = 0; t < TT; t++) accv += tl[t] * Wh[t * HHEAD + tid];
        hh[tid] = accv;
    }
    __syncthreads();
    float accv = vbh[tid];
#pragma unroll 8
    for (int j = 0; j < HHEAD; j++) accv += hh[j] * Wh[tid * HHEAD + j];
    out[tid] = accv;                 // head_out occupies out[0..63]
}

extern "C" void kernel_launch(void* const* d_in, const int* in_sizes, int n_in,
                              void* d_out, int out_size) {
    const float* x        = (const float*)d_in[0];
    const int*   clusters = (const int*)  d_in[1];
    const float* Wt       = (const float*)d_in[2];
    const float* hb       = (const float*)d_in[3];
    const float* vb       = (const float*)d_in[4];
    const float* Wh       = (const float*)d_in[5];
    const float* hbh      = (const float*)d_in[6];
    const float* vbh      = (const float*)d_in[7];
    float* out = (float*)d_out;

    zero_kernel<<<(TT * CC * CC + 255) / 256, 256>>>();
    gram_kernel<<<dim3(TT, CHUNKS), 256>>>(x, clusters);
    finalize_kernel<<<TT, 32>>>(Wt, hb, vb, out);
    head_kernel<<<1, TT>>>(Wh, hbh, vbh, out);
}